// round 2
// baseline (speedup 1.0000x reference)
#include <cuda_runtime.h>

// Problem constants
#define PP      128                 // polygons
#define NN      128                 // pred points per polygon per level
#define MM      1024                // gt points per polygon
#define CHUNKS  8
#define CM      (MM/CHUNKS)         // 128 gt points per chunk
#define LVL_STRIDE (PP*NN)          // 16384

// level weights / (3 * P * N)
#define W0 (0.2f/49152.0f)
#define W1 (0.3f/49152.0f)
#define W2 (0.5f/49152.0f)

typedef unsigned long long u64;

// Scratch (no allocations allowed)
__device__ float g_partial[CHUNKS][3 * LVL_STRIDE];  // min d^2 per (chunk, level, point)
__device__ float g_poly[PP];                         // per-polygon weighted sums
__device__ int   g_cnt[PP];                          // per-polygon arrival counters (zero-init)
__device__ int   g_cnt2;                             // polygon-combiner counter (zero-init)

// ---- packed f32x2 helpers (sm_103a) ----
__device__ __forceinline__ u64 pack2(float x) {
    u64 r; asm("mov.b64 %0, {%1, %1};" : "=l"(r) : "f"(x)); return r;
}
__device__ __forceinline__ u64 packf2(float x, float y) {
    u64 r; asm("mov.b64 %0, {%1, %2};" : "=l"(r) : "f"(x), "f"(y)); return r;
}
__device__ __forceinline__ u64 fma2(u64 a, u64 b, u64 c) {
    u64 d; asm("fma.rn.f32x2 %0, %1, %2, %3;" : "=l"(d) : "l"(a), "l"(b), "l"(c)); return d;
}
__device__ __forceinline__ void unpack2(u64 v, float& lo, float& hi) {
    asm("mov.b64 {%0, %1}, %2;" : "=f"(lo), "=f"(hi) : "l"(v));
}

// Single fused kernel. Grid: (CHUNKS, PP), 128 threads.
// Phase 1: each CTA computes partial min-d^2 over its 128-gt chunk for 3 levels.
// Phase 2: last CTA per polygon combines chunks -> weighted per-polygon sum.
// Phase 3: last polygon-combiner sums 128 polygon scalars -> *out.
__global__ __launch_bounds__(128) void k_fused(
    const float* __restrict__ pred0, const float* __restrict__ pred1,
    const float* __restrict__ pred2, const float* __restrict__ gt,
    float* __restrict__ out)
{
    // smem: A/B packed for LDS.128, C packed for LDS.64
    __shared__ __align__(16) float4 sAB[CM / 2];  // (a_lo, a_hi, b_lo, b_hi)
    __shared__ __align__(16) float2 sC[CM / 2];   // (c_lo, c_hi)
    __shared__ int s_ticket;
    __shared__ float s_red[128];

    const int ch  = blockIdx.x;
    const int p   = blockIdx.y;
    const int tid = threadIdx.x;

    // ---- Phase 1: load gt chunk, precompute A=-2gx, B=-2gy, C=|g|^2 ----
    {
        const float2* gsrc = (const float2*)(gt + ((size_t)p * MM + (size_t)ch * CM) * 2);
        float2 g = gsrc[tid];
        int i = tid >> 1, sl = tid & 1;
        ((float*)&sAB[i])[sl]     = -2.0f * g.x;
        ((float*)&sAB[i])[2 + sl] = -2.0f * g.y;
        ((float*)&sC[i])[sl]      = fmaf(g.x, g.x, g.y * g.y);
    }

    // this thread's 3 points (same n across levels); coords are [...,1:] of last dim 3
    const int base = (p * NN + tid) * 3;
    const float x0 = pred0[base + 1], y0 = pred0[base + 2];
    const float x1 = pred1[base + 1], y1 = pred1[base + 2];
    const float x2 = pred2[base + 1], y2 = pred2[base + 2];
    __syncthreads();

    const u64 X0 = pack2(x0), Y0 = pack2(y0);
    const u64 X1 = pack2(x1), Y1 = pack2(y1);
    const u64 X2 = pack2(x2), Y2 = pack2(y2);

    const float INF = __int_as_float(0x7f800000);
    float m0l = INF, m0h = INF, m1l = INF, m1h = INF, m2l = INF, m2h = INF;

    #pragma unroll 8
    for (int i = 0; i < CM / 2; i++) {
        float4 ab = sAB[i];                    // LDS.128, warp-broadcast
        float2 cc = sC[i];                     // LDS.64
        u64 a = packf2(ab.x, ab.y);
        u64 b = packf2(ab.z, ab.w);
        u64 c = packf2(cc.x, cc.y);
        u64 t0 = fma2(Y0, b, fma2(X0, a, c)); // t = C + A*px + B*py  (2 gt packed)
        u64 t1 = fma2(Y1, b, fma2(X1, a, c));
        u64 t2 = fma2(Y2, b, fma2(X2, a, c));
        float lo, hi;
        unpack2(t0, lo, hi); m0l = fminf(m0l, lo); m0h = fminf(m0h, hi);
        unpack2(t1, lo, hi); m1l = fminf(m1l, lo); m1h = fminf(m1h, hi);
        unpack2(t2, lo, hi); m2l = fminf(m2l, lo); m2h = fminf(m2h, hi);
    }

    const int pt = p * NN + tid;
    g_partial[ch][0 * LVL_STRIDE + pt] = fminf(m0l, m0h) + fmaf(x0, x0, y0 * y0);
    g_partial[ch][1 * LVL_STRIDE + pt] = fminf(m1l, m1h) + fmaf(x1, x1, y1 * y1);
    g_partial[ch][2 * LVL_STRIDE + pt] = fminf(m2l, m2h) + fmaf(x2, x2, y2 * y2);

    // ---- Phase 2: last CTA of this polygon combines all chunks ----
    __threadfence();                 // release our g_partial writes (every thread)
    __syncthreads();
    if (tid == 0) s_ticket = atomicAdd(&g_cnt[p], 1);
    __syncthreads();
    if (s_ticket != CHUNKS - 1) return;

    // We are the last arriver for polygon p: all chunks' writes are visible.
    float s = 0.0f;
    #pragma unroll
    for (int l = 0; l < 3; l++) {
        const int idx = l * LVL_STRIDE + p * NN + tid;
        float v = __ldcg(&g_partial[0][idx]);
        #pragma unroll
        for (int c = 1; c < CHUNKS; c++)
            v = fminf(v, __ldcg(&g_partial[c][idx]));
        float d = sqrtf(fmaxf(v, 0.0f));
        float w = (l == 0) ? W0 : ((l == 1) ? W1 : W2);
        s = fmaf(w, d, s);
    }
    s_red[tid] = s;
    __syncthreads();
    #pragma unroll
    for (int off = 64; off > 0; off >>= 1) {
        if (tid < off) s_red[tid] += s_red[tid + off];
        __syncthreads();
    }

    if (tid == 0) {
        g_poly[p] = s_red[0];
        g_cnt[p] = 0;                        // reset for next graph replay
        __threadfence();                     // release g_poly[p]
        int t2 = atomicAdd(&g_cnt2, 1);
        if (t2 == PP - 1) {
            __threadfence();
            // ---- Phase 3: final deterministic sum over polygons ----
            float tot = 0.0f;
            #pragma unroll
            for (int i = 0; i < PP; i++) tot += __ldcg(&g_poly[i]);
            *out = tot;
            g_cnt2 = 0;                      // reset for next graph replay
        }
    }
}

extern "C" void kernel_launch(void* const* d_in, const int* in_sizes, int n_in,
                              void* d_out, int out_size)
{
    const float* pred0 = (const float*)d_in[0];
    const float* pred1 = (const float*)d_in[1];
    const float* pred2 = (const float*)d_in[2];
    const float* gt    = (const float*)d_in[3];

    dim3 grid(CHUNKS, PP);
    k_fused<<<grid, 128>>>(pred0, pred1, pred2, gt, (float*)d_out);
}

// round 4
// speedup vs baseline: 1.0449x; 1.0449x over previous
#include <cuda_runtime.h>

// Problem constants
#define PP      128                 // polygons
#define NN      128                 // pred points per polygon per level
#define MM      1024                // gt points per polygon
#define CHUNKS  8
#define CM      (MM/CHUNKS)         // 128 gt points per chunk
#define LVL_STRIDE (PP*NN)          // 16384

// level weights / (3 * P * N)
#define W0 (0.2f/49152.0f)
#define W1 (0.3f/49152.0f)
#define W2 (0.5f/49152.0f)

typedef unsigned long long u64;

// Scratch (no allocations allowed)
__device__ float g_partial[CHUNKS][3 * LVL_STRIDE];  // min d^2 per (chunk, level, point)
__device__ float g_poly[PP];                         // per-polygon weighted sums
__device__ int   g_cnt[PP];                          // per-polygon arrival counters (zero-init)
__device__ int   g_cnt2;                             // polygon-combiner counter (zero-init)

// ---- packed f32x2 helpers (sm_103a) ----
__device__ __forceinline__ u64 pack2(float x) {
    u64 r; asm("mov.b64 %0, {%1, %1};" : "=l"(r) : "f"(x)); return r;
}
__device__ __forceinline__ u64 fma2(u64 a, u64 b, u64 c) {
    u64 d; asm("fma.rn.f32x2 %0, %1, %2, %3;" : "=l"(d) : "l"(a), "l"(b), "l"(c)); return d;
}
__device__ __forceinline__ void unpack2(u64 v, float& lo, float& hi) {
    asm("mov.b64 {%0, %1}, %2;" : "=f"(lo), "=f"(hi) : "l"(v));
}
// One LDS.128 -> two u64 f32x2 operands, no repacking
__device__ __forceinline__ void lds2x64(u64& p0, u64& p1, const float* s) {
    unsigned a = (unsigned)__cvta_generic_to_shared(s);
    asm volatile("ld.shared.v2.u64 {%0, %1}, [%2];" : "=l"(p0), "=l"(p1) : "r"(a));
}

// Single fused kernel. Grid: (CHUNKS, PP), 128 threads.
__global__ __launch_bounds__(128) void k_fused(
    const float* __restrict__ pred0, const float* __restrict__ pred1,
    const float* __restrict__ pred2, const float* __restrict__ gt,
    float* __restrict__ out)
{
    __shared__ __align__(16) float sA[CM];
    __shared__ __align__(16) float sB[CM];
    __shared__ __align__(16) float sC[CM];
    __shared__ int s_ticket;
    __shared__ float s_red[128];

    const int ch  = blockIdx.x;
    const int p   = blockIdx.y;
    const int tid = threadIdx.x;

    // ---- Phase 1: load gt chunk, precompute A=-2gx, B=-2gy, C=|g|^2 ----
    {
        const float2* gsrc = (const float2*)(gt + ((size_t)p * MM + (size_t)ch * CM) * 2);
        float2 g = gsrc[tid];
        sA[tid] = -2.0f * g.x;
        sB[tid] = -2.0f * g.y;
        sC[tid] = fmaf(g.x, g.x, g.y * g.y);
    }

    // this thread's 3 points (same n across levels); coords are [...,1:] of last dim 3
    const int base = (p * NN + tid) * 3;
    const float x0 = pred0[base + 1], y0 = pred0[base + 2];
    const float x1 = pred1[base + 1], y1 = pred1[base + 2];
    const float x2 = pred2[base + 1], y2 = pred2[base + 2];
    __syncthreads();

    const u64 X0 = pack2(x0), Y0 = pack2(y0);
    const u64 X1 = pack2(x1), Y1 = pack2(y1);
    const u64 X2 = pack2(x2), Y2 = pack2(y2);

    const float INF = __int_as_float(0x7f800000);
    // 12 independent scalar accumulators: [level][slot]
    float m00 = INF, m01 = INF, m02 = INF, m03 = INF;
    float m10 = INF, m11 = INF, m12 = INF, m13 = INF;
    float m20 = INF, m21 = INF, m22 = INF, m23 = INF;

    #pragma unroll 8
    for (int i = 0; i < CM / 4; i++) {        // 4 gt points per iteration
        u64 a0, a1, b0, b1, c0, c1;
        lds2x64(a0, a1, sA + 4 * i);          // 3x LDS.128, warp-broadcast
        lds2x64(b0, b1, sB + 4 * i);
        lds2x64(c0, c1, sC + 4 * i);
        float lo, hi;
        // level 0
        unpack2(fma2(Y0, b0, fma2(X0, a0, c0)), lo, hi);
        m00 = fminf(m00, lo); m01 = fminf(m01, hi);
        unpack2(fma2(Y0, b1, fma2(X0, a1, c1)), lo, hi);
        m02 = fminf(m02, lo); m03 = fminf(m03, hi);
        // level 1
        unpack2(fma2(Y1, b0, fma2(X1, a0, c0)), lo, hi);
        m10 = fminf(m10, lo); m11 = fminf(m11, hi);
        unpack2(fma2(Y1, b1, fma2(X1, a1, c1)), lo, hi);
        m12 = fminf(m12, lo); m13 = fminf(m13, hi);
        // level 2
        unpack2(fma2(Y2, b0, fma2(X2, a0, c0)), lo, hi);
        m20 = fminf(m20, lo); m21 = fminf(m21, hi);
        unpack2(fma2(Y2, b1, fma2(X2, a1, c1)), lo, hi);
        m22 = fminf(m22, lo); m23 = fminf(m23, hi);
    }

    const int pt = p * NN + tid;
    g_partial[ch][0 * LVL_STRIDE + pt] =
        fminf(fminf(m00, m01), fminf(m02, m03)) + fmaf(x0, x0, y0 * y0);
    g_partial[ch][1 * LVL_STRIDE + pt] =
        fminf(fminf(m10, m11), fminf(m12, m13)) + fmaf(x1, x1, y1 * y1);
    g_partial[ch][2 * LVL_STRIDE + pt] =
        fminf(fminf(m20, m21), fminf(m22, m23)) + fmaf(x2, x2, y2 * y2);

    // ---- Phase 2: last CTA of this polygon combines all chunks ----
    __threadfence();                 // release our g_partial writes
    __syncthreads();
    if (tid == 0) s_ticket = atomicAdd(&g_cnt[p], 1);
    __syncthreads();
    if (s_ticket != CHUNKS - 1) return;

    float s = 0.0f;
    #pragma unroll
    for (int l = 0; l < 3; l++) {
        const int idx = l * LVL_STRIDE + p * NN + tid;
        float v = __ldcg(&g_partial[0][idx]);
        #pragma unroll
        for (int c = 1; c < CHUNKS; c++)
            v = fminf(v, __ldcg(&g_partial[c][idx]));
        float d = sqrtf(fmaxf(v, 0.0f));
        float w = (l == 0) ? W0 : ((l == 1) ? W1 : W2);
        s = fmaf(w, d, s);
    }
    s_red[tid] = s;
    __syncthreads();
    #pragma unroll
    for (int off = 64; off > 0; off >>= 1) {
        if (tid < off) s_red[tid] += s_red[tid + off];
        __syncthreads();
    }

    if (tid == 0) {
        g_poly[p] = s_red[0];
        g_cnt[p] = 0;                        // reset for next graph replay
        __threadfence();                     // release g_poly[p]
        int t2 = atomicAdd(&g_cnt2, 1);
        if (t2 == PP - 1) {
            __threadfence();
            // ---- Phase 3: final deterministic sum over polygons ----
            float tot = 0.0f;
            #pragma unroll
            for (int i = 0; i < PP; i++) tot += __ldcg(&g_poly[i]);
            *out = tot;
            g_cnt2 = 0;                      // reset for next graph replay
        }
    }
}

extern "C" void kernel_launch(void* const* d_in, const int* in_sizes, int n_in,
                              void* d_out, int out_size)
{
    const float* pred0 = (const float*)d_in[0];
    const float* pred1 = (const float*)d_in[1];
    const float* pred2 = (const float*)d_in[2];
    const float* gt    = (const float*)d_in[3];

    dim3 grid(CHUNKS, PP);
    k_fused<<<grid, 128>>>(pred0, pred1, pred2, gt, (float*)d_out);
}

// round 5
// speedup vs baseline: 1.0470x; 1.0020x over previous
#include <cuda_runtime.h>

// Problem constants
#define PP      128                 // polygons
#define NN      128                 // pred points per polygon per level
#define MM      1024                // gt points per polygon
#define CHUNKS  16
#define CM      (MM/CHUNKS)         // 64 gt points per chunk
#define LVL_STRIDE (PP*NN)          // 16384

// level weights / (3 * P * N)
#define W0 (0.2f/49152.0f)
#define W1 (0.3f/49152.0f)
#define W2 (0.5f/49152.0f)

typedef unsigned long long u64;

// Scratch (no allocations allowed)
__device__ float g_partial[CHUNKS][3 * LVL_STRIDE];  // min d^2 per (chunk, level, point)
__device__ float g_poly[PP];                         // per-polygon weighted sums
__device__ int   g_cnt[PP];                          // per-polygon arrival counters (zero-init)
__device__ int   g_cnt2;                             // polygon-combiner counter (zero-init)

// ---- packed f32x2 helpers (sm_103a). fma2 is pure (non-volatile): schedulable. ----
__device__ __forceinline__ u64 pack2(float x) {
    u64 r; asm("mov.b64 %0, {%1, %1};" : "=l"(r) : "f"(x)); return r;
}
__device__ __forceinline__ u64 fma2(u64 a, u64 b, u64 c) {
    u64 d; asm("fma.rn.f32x2 %0, %1, %2, %3;" : "=l"(d) : "l"(a), "l"(b), "l"(c)); return d;
}
// Min packed halves into two scalar accumulators; sub-register access, no MOVs.
__device__ __forceinline__ void min2acc(float& m0, float& m1, u64 t) {
    float2 f = *reinterpret_cast<float2*>(&t);
    m0 = fminf(m0, f.x);
    m1 = fminf(m1, f.y);
}

// Single fused kernel. Grid: (CHUNKS, PP), 128 threads.
__global__ __launch_bounds__(128) void k_fused(
    const float* __restrict__ pred0, const float* __restrict__ pred1,
    const float* __restrict__ pred2, const float* __restrict__ gt,
    float* __restrict__ out)
{
    __shared__ __align__(16) float sA[CM];
    __shared__ __align__(16) float sB[CM];
    __shared__ __align__(16) float sC[CM];
    __shared__ int s_ticket;
    __shared__ int s_final;
    __shared__ float s_red[128];

    const int ch  = blockIdx.x;
    const int p   = blockIdx.y;
    const int tid = threadIdx.x;

    // ---- Phase 1: load gt chunk, precompute A=-2gx, B=-2gy, C=|g|^2 ----
    if (tid < CM) {
        const float2* gsrc = (const float2*)(gt + ((size_t)p * MM + (size_t)ch * CM) * 2);
        float2 g = gsrc[tid];
        sA[tid] = -2.0f * g.x;
        sB[tid] = -2.0f * g.y;
        sC[tid] = fmaf(g.x, g.x, g.y * g.y);
    }

    // this thread's 3 points (same n across levels); coords are [...,1:] of last dim 3
    const int base = (p * NN + tid) * 3;
    const float x0 = pred0[base + 1], y0 = pred0[base + 2];
    const float x1 = pred1[base + 1], y1 = pred1[base + 2];
    const float x2 = pred2[base + 1], y2 = pred2[base + 2];
    __syncthreads();

    const u64 X0 = pack2(x0), Y0 = pack2(y0);
    const u64 X1 = pack2(x1), Y1 = pack2(y1);
    const u64 X2 = pack2(x2), Y2 = pack2(y2);

    const float INF = __int_as_float(0x7f800000);
    // 12 independent scalar accumulators: [level][slot]
    float m00 = INF, m01 = INF, m02 = INF, m03 = INF;
    float m10 = INF, m11 = INF, m12 = INF, m13 = INF;
    float m20 = INF, m21 = INF, m22 = INF, m23 = INF;

    const ulonglong2* A2 = (const ulonglong2*)sA;   // plain derefs -> schedulable LDS.128
    const ulonglong2* B2 = (const ulonglong2*)sB;
    const ulonglong2* C2 = (const ulonglong2*)sC;

    #pragma unroll 4
    for (int i = 0; i < CM / 4; i++) {              // 4 gt points per iteration
        ulonglong2 av = A2[i], bv = B2[i], cv = C2[i];
        // level 0
        min2acc(m00, m01, fma2(Y0, bv.x, fma2(X0, av.x, cv.x)));
        min2acc(m02, m03, fma2(Y0, bv.y, fma2(X0, av.y, cv.y)));
        // level 1
        min2acc(m10, m11, fma2(Y1, bv.x, fma2(X1, av.x, cv.x)));
        min2acc(m12, m13, fma2(Y1, bv.y, fma2(X1, av.y, cv.y)));
        // level 2
        min2acc(m20, m21, fma2(Y2, bv.x, fma2(X2, av.x, cv.x)));
        min2acc(m22, m23, fma2(Y2, bv.y, fma2(X2, av.y, cv.y)));
    }

    const int pt = p * NN + tid;
    g_partial[ch][0 * LVL_STRIDE + pt] =
        fminf(fminf(m00, m01), fminf(m02, m03)) + fmaf(x0, x0, y0 * y0);
    g_partial[ch][1 * LVL_STRIDE + pt] =
        fminf(fminf(m10, m11), fminf(m12, m13)) + fmaf(x1, x1, y1 * y1);
    g_partial[ch][2 * LVL_STRIDE + pt] =
        fminf(fminf(m20, m21), fminf(m22, m23)) + fmaf(x2, x2, y2 * y2);

    // ---- Phase 2: last CTA of this polygon combines all chunks ----
    __threadfence();                 // release our g_partial writes
    __syncthreads();
    if (tid == 0) s_ticket = atomicAdd(&g_cnt[p], 1);
    __syncthreads();
    if (s_ticket != CHUNKS - 1) return;

    float s = 0.0f;
    #pragma unroll
    for (int l = 0; l < 3; l++) {
        const int idx = l * LVL_STRIDE + p * NN + tid;
        float v = __ldcg(&g_partial[0][idx]);
        #pragma unroll
        for (int c = 1; c < CHUNKS; c++)
            v = fminf(v, __ldcg(&g_partial[c][idx]));
        float d = sqrtf(fmaxf(v, 0.0f));
        float w = (l == 0) ? W0 : ((l == 1) ? W1 : W2);
        s = fmaf(w, d, s);
    }
    s_red[tid] = s;
    __syncthreads();
    #pragma unroll
    for (int off = 64; off > 0; off >>= 1) {
        if (tid < off) s_red[tid] += s_red[tid + off];
        __syncthreads();
    }

    // ---- Phase 3: last polygon-combiner CTA sums 128 polygon scalars ----
    if (tid == 0) {
        g_poly[p] = s_red[0];
        g_cnt[p] = 0;                        // reset for next graph replay
        __threadfence();                     // release g_poly[p]
        int t2 = atomicAdd(&g_cnt2, 1);
        s_final = (t2 == PP - 1);
        if (s_final) g_cnt2 = 0;             // reset for next graph replay
    }
    __syncthreads();
    if (!s_final) return;

    __threadfence();                         // acquire other CTAs' g_poly writes
    s_red[tid] = __ldcg(&g_poly[tid]);       // PP == blockDim.x == 128
    __syncthreads();
    #pragma unroll
    for (int off = 64; off > 0; off >>= 1) {
        if (tid < off) s_red[tid] += s_red[tid + off];
        __syncthreads();
    }
    if (tid == 0) *out = s_red[0];
}

extern "C" void kernel_launch(void* const* d_in, const int* in_sizes, int n_in,
                              void* d_out, int out_size)
{
    const float* pred0 = (const float*)d_in[0];
    const float* pred1 = (const float*)d_in[1];
    const float* pred2 = (const float*)d_in[2];
    const float* gt    = (const float*)d_in[3];

    dim3 grid(CHUNKS, PP);
    k_fused<<<grid, 128>>>(pred0, pred1, pred2, gt, (float*)d_out);
}

// round 6
// speedup vs baseline: 1.1481x; 1.0966x over previous
#include <cuda_runtime.h>

// Problem constants
#define PP      128                 // polygons
#define NN      128                 // pred points per polygon per level
#define MM      1024                // gt points per polygon
#define CHUNKS  8
#define CM      (MM/CHUNKS)         // 128 gt points per chunk
#define LVL_STRIDE (PP*NN)          // 16384

// level weights / (3 * P * N)
#define W0 (0.2f/49152.0f)
#define W1 (0.3f/49152.0f)
#define W2 (0.5f/49152.0f)

typedef unsigned long long u64;

// Scratch (no allocations allowed)
__device__ float g_partial[CHUNKS][3 * LVL_STRIDE];  // min d^2 per (chunk, level, point)
__device__ float g_poly[PP];                         // per-polygon weighted sums
__device__ int   g_cnt2;                             // tail counter (zero-init)

// ---- packed f32x2 helpers (sm_103a). fma2 is pure (non-volatile): schedulable. ----
__device__ __forceinline__ u64 pack2(float x) {
    u64 r; asm("mov.b64 %0, {%1, %1};" : "=l"(r) : "f"(x)); return r;
}
__device__ __forceinline__ u64 fma2(u64 a, u64 b, u64 c) {
    u64 d; asm("fma.rn.f32x2 %0, %1, %2, %3;" : "=l"(d) : "l"(a), "l"(b), "l"(c)); return d;
}
// Min packed halves into two scalar accumulators; sub-register access.
__device__ __forceinline__ void min2acc(float& m0, float& m1, u64 t) {
    float2 f = *reinterpret_cast<float2*>(&t);
    m0 = fminf(m0, f.x);
    m1 = fminf(m1, f.y);
}

// Hot kernel: grid (CHUNKS, PP), 64 threads; each thread owns 2 points x 3 levels.
// NO fences, NO atomics — ordering comes from the kernel boundary.
__global__ __launch_bounds__(64) void k_partial(
    const float* __restrict__ pred0, const float* __restrict__ pred1,
    const float* __restrict__ pred2, const float* __restrict__ gt)
{
    __shared__ __align__(16) float sA[CM];
    __shared__ __align__(16) float sB[CM];
    __shared__ __align__(16) float sC[CM];

    const int ch  = blockIdx.x;
    const int p   = blockIdx.y;
    const int tid = threadIdx.x;

    // Load gt chunk, precompute A=-2gx, B=-2gy, C=|g|^2  (128 pts by 64 threads)
    {
        const float2* gsrc = (const float2*)(gt + ((size_t)p * MM + (size_t)ch * CM) * 2);
        #pragma unroll
        for (int k = 0; k < 2; k++) {
            int m = tid + k * 64;
            float2 g = gsrc[m];
            sA[m] = -2.0f * g.x;
            sB[m] = -2.0f * g.y;
            sC[m] = fmaf(g.x, g.x, g.y * g.y);
        }
    }

    // Two points per thread, 3 levels each; coords are [...,1:] of last dim 3
    const int n0 = 2 * tid, n1 = 2 * tid + 1;
    const int ba = (p * NN + n0) * 3;
    const int bb = (p * NN + n1) * 3;
    const float x0a = pred0[ba + 1], y0a = pred0[ba + 2];
    const float x1a = pred1[ba + 1], y1a = pred1[ba + 2];
    const float x2a = pred2[ba + 1], y2a = pred2[ba + 2];
    const float x0b = pred0[bb + 1], y0b = pred0[bb + 2];
    const float x1b = pred1[bb + 1], y1b = pred1[bb + 2];
    const float x2b = pred2[bb + 1], y2b = pred2[bb + 2];
    __syncthreads();

    const u64 X0a = pack2(x0a), Y0a = pack2(y0a), X0b = pack2(x0b), Y0b = pack2(y0b);
    const u64 X1a = pack2(x1a), Y1a = pack2(y1a), X1b = pack2(x1b), Y1b = pack2(y1b);
    const u64 X2a = pack2(x2a), Y2a = pack2(y2a), X2b = pack2(x2b), Y2b = pack2(y2b);

    const float INF = __int_as_float(0x7f800000);
    float m0a0 = INF, m0a1 = INF, m0b0 = INF, m0b1 = INF;
    float m1a0 = INF, m1a1 = INF, m1b0 = INF, m1b1 = INF;
    float m2a0 = INF, m2a1 = INF, m2b0 = INF, m2b1 = INF;

    const ulonglong2* A2 = (const ulonglong2*)sA;   // plain derefs -> schedulable LDS.128
    const ulonglong2* B2 = (const ulonglong2*)sB;
    const ulonglong2* C2 = (const ulonglong2*)sC;

    #pragma unroll 8
    for (int i = 0; i < CM / 4; i++) {              // 4 gt points per iteration
        ulonglong2 av = A2[i], bv = B2[i], cv = C2[i];
        // level 0
        min2acc(m0a0, m0a1, fma2(Y0a, bv.x, fma2(X0a, av.x, cv.x)));
        min2acc(m0a0, m0a1, fma2(Y0a, bv.y, fma2(X0a, av.y, cv.y)));
        min2acc(m0b0, m0b1, fma2(Y0b, bv.x, fma2(X0b, av.x, cv.x)));
        min2acc(m0b0, m0b1, fma2(Y0b, bv.y, fma2(X0b, av.y, cv.y)));
        // level 1
        min2acc(m1a0, m1a1, fma2(Y1a, bv.x, fma2(X1a, av.x, cv.x)));
        min2acc(m1a0, m1a1, fma2(Y1a, bv.y, fma2(X1a, av.y, cv.y)));
        min2acc(m1b0, m1b1, fma2(Y1b, bv.x, fma2(X1b, av.x, cv.x)));
        min2acc(m1b0, m1b1, fma2(Y1b, bv.y, fma2(X1b, av.y, cv.y)));
        // level 2
        min2acc(m2a0, m2a1, fma2(Y2a, bv.x, fma2(X2a, av.x, cv.x)));
        min2acc(m2a0, m2a1, fma2(Y2a, bv.y, fma2(X2a, av.y, cv.y)));
        min2acc(m2b0, m2b1, fma2(Y2b, bv.x, fma2(X2b, av.x, cv.x)));
        min2acc(m2b0, m2b1, fma2(Y2b, bv.y, fma2(X2b, av.y, cv.y)));
    }

    const int pta = p * NN + n0;
    const int ptb = p * NN + n1;
    g_partial[ch][0 * LVL_STRIDE + pta] = fminf(m0a0, m0a1) + fmaf(x0a, x0a, y0a * y0a);
    g_partial[ch][0 * LVL_STRIDE + ptb] = fminf(m0b0, m0b1) + fmaf(x0b, x0b, y0b * y0b);
    g_partial[ch][1 * LVL_STRIDE + pta] = fminf(m1a0, m1a1) + fmaf(x1a, x1a, y1a * y1a);
    g_partial[ch][1 * LVL_STRIDE + ptb] = fminf(m1b0, m1b1) + fmaf(x1b, x1b, y1b * y1b);
    g_partial[ch][2 * LVL_STRIDE + pta] = fminf(m2a0, m2a1) + fmaf(x2a, x2a, y2a * y2a);
    g_partial[ch][2 * LVL_STRIDE + ptb] = fminf(m2b0, m2b1) + fmaf(x2b, x2b, y2b * y2b);
}

// Tail kernel: grid (PP), 128 threads. Combine chunks -> per-polygon weighted sum;
// last CTA reduces the 128 polygon scalars.
__global__ __launch_bounds__(128) void k_tail(float* __restrict__ out)
{
    __shared__ float s_red[128];
    __shared__ int s_final;

    const int p   = blockIdx.x;
    const int tid = threadIdx.x;

    float s = 0.0f;
    #pragma unroll
    for (int l = 0; l < 3; l++) {
        const int idx = l * LVL_STRIDE + p * NN + tid;
        float v = g_partial[0][idx];
        #pragma unroll
        for (int c = 1; c < CHUNKS; c++)
            v = fminf(v, g_partial[c][idx]);
        float d = sqrtf(fmaxf(v, 0.0f));
        float w = (l == 0) ? W0 : ((l == 1) ? W1 : W2);
        s = fmaf(w, d, s);
    }
    s_red[tid] = s;
    __syncthreads();
    #pragma unroll
    for (int off = 64; off > 0; off >>= 1) {
        if (tid < off) s_red[tid] += s_red[tid + off];
        __syncthreads();
    }

    if (tid == 0) {
        g_poly[p] = s_red[0];
        __threadfence();                     // release g_poly[p]
        int t2 = atomicAdd(&g_cnt2, 1);
        s_final = (t2 == PP - 1);
        if (s_final) g_cnt2 = 0;             // reset for next graph replay
    }
    __syncthreads();
    if (!s_final) return;

    __threadfence();                         // acquire other CTAs' g_poly writes
    s_red[tid] = __ldcg(&g_poly[tid]);       // PP == blockDim.x == 128
    __syncthreads();
    #pragma unroll
    for (int off = 64; off > 0; off >>= 1) {
        if (tid < off) s_red[tid] += s_red[tid + off];
        __syncthreads();
    }
    if (tid == 0) *out = s_red[0];
}

extern "C" void kernel_launch(void* const* d_in, const int* in_sizes, int n_in,
                              void* d_out, int out_size)
{
    const float* pred0 = (const float*)d_in[0];
    const float* pred1 = (const float*)d_in[1];
    const float* pred2 = (const float*)d_in[2];
    const float* gt    = (const float*)d_in[3];

    dim3 grid(CHUNKS, PP);
    k_partial<<<grid, 64>>>(pred0, pred1, pred2, gt);
    k_tail<<<PP, 128>>>((float*)d_out);
}